// round 12
// baseline (speedup 1.0000x reference)
#include <cuda_runtime.h>
#include <cuda_fp16.h>
#include <cstdint>
#include <cstddef>

#define NROWS 8192
#define H 1024

// ======================= helpers =======================
__device__ __forceinline__ uint32_t smem_to_u32(const void* p) {
    uint32_t a;
    asm("{ .reg .u64 t; cvta.to.shared.u64 t, %1; cvt.u32.u64 %0, t; }" : "=r"(a) : "l"(p));
    return a;
}
__device__ __forceinline__ void ldmatrix_x4(uint32_t* r, uint32_t addr) {
    asm volatile("ldmatrix.sync.aligned.m8n8.x4.shared.b16 {%0,%1,%2,%3}, [%4];"
                 : "=r"(r[0]), "=r"(r[1]), "=r"(r[2]), "=r"(r[3]) : "r"(addr));
}
__device__ __forceinline__ void mma_16816(float* d, const uint32_t* a, uint32_t b0, uint32_t b1) {
    asm volatile(
        "mma.sync.aligned.m16n8k16.row.col.f32.f16.f16.f32 "
        "{%0,%1,%2,%3}, {%4,%5,%6,%7}, {%8,%9}, {%0,%1,%2,%3};"
        : "+f"(d[0]), "+f"(d[1]), "+f"(d[2]), "+f"(d[3])
        : "r"(a[0]), "r"(a[1]), "r"(a[2]), "r"(a[3]), "r"(b0), "r"(b1));
}
__device__ __forceinline__ void cp_async16(uint32_t saddr, const void* gaddr) {
    asm volatile("cp.async.cg.shared.global [%0], [%1], 16;" :: "r"(saddr), "l"(gaddr));
}
__device__ __forceinline__ void fp16_split(float v, __half& h, __half& l) {
    h = __float2half(v);
    l = __float2half(v - __half2float(h));
}

// ======================= scratch (device globals only) =======================
__device__ __align__(256) float g_cpart[8 * H * H];   // split-K partials; slice 7 = A1 fp32
__device__ __align__(256) float g_spart[32 * H];
__device__ float g_s[H];
__device__ float g_ks[H];
__device__ float g_vs[H];
__device__ float g_vsp[H];
__device__ float g_c[H];
__device__ float g_u1[H];
__device__ float g_u2[H];
__device__ float g_w1[H];
__device__ float g_w2[H];
__device__ float g_d2[2];

__device__ __align__(256) __half g_xt_hi[H * NROWS];   // x^T fp16 hi/lo
__device__ __align__(256) __half g_xt_lo[H * NROWS];
__device__ __align__(256) __half g_x_h[NROWS * H];     // fp16(x), direct layout
__device__ __align__(256) __half g_wkt_hi[H * H], g_wkt_lo[H * H];  // Wk^T split
__device__ __align__(256) __half g_wv_hi[H * H],  g_wv_lo[H * H];   // Wv split (row-major)
__device__ __align__(256) __half g_wqt_hi[H * H], g_wqt_lo[H * H];  // Wq^T split
__device__ __align__(256) __half g_a1_hi[H * H],  g_a1_lo[H * H];   // A1 = Wq^T Wk split
__device__ __align__(256) __half g_g_hi[H * H],   g_g_lo[H * H];    // G split (symmetric)
__device__ __align__(256) __half g_u_hi[H * H],   g_u_lo[H * H];    // U = A1 G split
__device__ __align__(256) __half g_pt_h[H * H];        // fp16(P)^T, single term

// ======================= HMMA GEMM: C = alpha * A @ B^T (+ addvec) =======================
// 256x128 CTA tile, 8 warps (4m x 2n), 64x64 warp tile, K-chunk 64, 3-stage cp.async ring.
// nseg segments of Kseg each (total K = nseg*Kseg). Ceil-division split-K over blockIdx.z.
// tri=1: lower-band block decode for symmetric x^T x (grid.x = 20 flattened blocks).
struct GemmArgs {
    const __half* A0; const __half* A1; const __half* A2;
    const __half* B0; const __half* B1; const __half* B2;
    int lda, ldb, Kseg;
    float* C; int ldc;
    float alpha;                 // applied only when Z==1
    const float* addvec;         // only when Z==1; may be null
    size_t partStride;           // slice stride when Z>1
    int tri;
    int nseg;
};

#define STAGE   49152                        // A 32KB + B 16KB
#define NSTAGE  3
#define GSMEM   (NSTAGE * STAGE)             // 147456

__global__ void __launch_bounds__(256, 1) mma_gemm(GemmArgs g) {
    extern __shared__ char smem[];
    const uint32_t sbase = smem_to_u32(smem);
    const int tid = threadIdx.x;
    const int wid = tid >> 5, lane = tid & 31;
    int bx, by;
    if (g.tri) {   // lower-band blocks: cumulative bases {0,2,6,12}
        const int idx = blockIdx.x;
        by = (idx < 2) ? 0 : (idx < 6) ? 1 : (idx < 12) ? 2 : 3;
        bx = idx - by * (by + 1);
    } else { bx = blockIdx.x; by = blockIdx.y; }
    const int m0 = by * 256, n0 = bx * 128;
    const int z = blockIdx.z, Z = gridDim.z;

    const int cps = g.Kseg >> 6;
    const int total = cps * g.nseg;
    const int ncz = (total + Z - 1) / Z;       // ceil
    const int c0 = z * ncz;
    const int c1 = (c0 + ncz < total) ? (c0 + ncz) : total;

    const __half* As[3] = {g.A0, g.A1, g.A2};
    const __half* Bs[3] = {g.B0, g.B1, g.B2};

    const int lrow = tid >> 3;          // 0..31
    const int lc16 = tid & 7;           // 16B column group

    auto issue = [&](int c, int st) {
        const int seg = c / cps;
        const int k0 = (c - seg * cps) << 6;
        const __half* Ap = As[seg] + (size_t)m0 * g.lda + k0;
        const __half* Bp = Bs[seg] + (size_t)n0 * g.ldb + k0;
        const uint32_t abase = sbase + st * STAGE;
        const uint32_t bbase = abase + 32768;
        #pragma unroll
        for (int p = 0; p < 8; p++) {   // A: 256 rows
            const int row = lrow + p * 32;
            const uint32_t so = row * 128 + ((lc16 ^ (row & 7)) << 4);
            cp_async16(abase + so, Ap + (size_t)row * g.lda + lc16 * 8);
        }
        #pragma unroll
        for (int p = 0; p < 4; p++) {   // B: 128 rows
            const int row = lrow + p * 32;
            const uint32_t so = row * 128 + ((lc16 ^ (row & 7)) << 4);
            cp_async16(bbase + so, Bp + (size_t)row * g.ldb + lc16 * 8);
        }
        asm volatile("cp.async.commit_group;" ::: "memory");
    };

    const int wm = wid >> 1;            // 0..3 -> 64 rows
    const int wn = wid & 1;             // 0..1 -> 64 cols
    const int t15 = lane & 15;
    const int khalf = (lane >> 4) & 1;

    float acc[4][8][4];
    #pragma unroll
    for (int i = 0; i < 4; i++)
        #pragma unroll
        for (int j = 0; j < 8; j++)
            #pragma unroll
            for (int q = 0; q < 4; q++) acc[i][j][q] = 0.f;

    if (c0 < c1) {
        issue(c0, 0);
        if (c0 + 1 < c1) issue(c0 + 1, 1);
        for (int c = c0; c < c1; c++) {
            const int st = (c - c0) % NSTAGE;
            if (c + 1 < c1) asm volatile("cp.async.wait_group 1;" ::: "memory");
            else            asm volatile("cp.async.wait_group 0;" ::: "memory");
            __syncthreads();
            if (c + 2 < c1) issue(c + 2, (st + 2) % NSTAGE);

            const uint32_t abase = sbase + st * STAGE;
            const uint32_t bbase = abase + 32768;
            #pragma unroll
            for (int kk = 0; kk < 4; kk++) {
                const int c16 = kk * 2 + khalf;
                uint32_t afr[4][4], bfr[4][4];
                #pragma unroll
                for (int mt = 0; mt < 4; mt++) {
                    const int row = wm * 64 + mt * 16 + t15;
                    ldmatrix_x4(afr[mt], abase + row * 128 + ((c16 ^ (row & 7)) << 4));
                }
                #pragma unroll
                for (int nt = 0; nt < 4; nt++) {
                    const int row = wn * 64 + nt * 16 + t15;
                    ldmatrix_x4(bfr[nt], bbase + row * 128 + ((c16 ^ (row & 7)) << 4));
                }
                #pragma unroll
                for (int mt = 0; mt < 4; mt++) {
                    #pragma unroll
                    for (int nt = 0; nt < 4; nt++) {
                        mma_16816(acc[mt][nt * 2 + 0], afr[mt], bfr[nt][0], bfr[nt][2]);
                        mma_16816(acc[mt][nt * 2 + 1], afr[mt], bfr[nt][1], bfr[nt][3]);
                    }
                }
            }
            __syncthreads();
        }
    }

    float* Cb = (Z == 1) ? g.C : (g.C + (size_t)z * g.partStride);
    #pragma unroll
    for (int mt = 0; mt < 4; mt++) {
        const int row = m0 + wm * 64 + mt * 16 + (lane >> 2);
        #pragma unroll
        for (int nt = 0; nt < 4; nt++) {
            #pragma unroll
            for (int gg = 0; gg < 2; gg++) {
                const int col = n0 + wn * 64 + nt * 16 + gg * 8 + 2 * (lane & 3);
                float* acc4 = acc[mt][nt * 2 + gg];
                float* p0 = Cb + (size_t)row * g.ldc + col;
                float* p1 = p0 + 8 * g.ldc;
                if (Z == 1) {
                    float av0 = 0.f, av1 = 0.f;
                    if (g.addvec) { av0 = g.addvec[col]; av1 = g.addvec[col + 1]; }
                    p0[0] = g.alpha * acc4[0] + av0;
                    p0[1] = g.alpha * acc4[1] + av1;
                    p1[0] = g.alpha * acc4[2] + av0;
                    p1[1] = g.alpha * acc4[3] + av1;
                } else {
                    p0[0] = acc4[0]; p0[1] = acc4[1];
                    p1[0] = acc4[2]; p1[1] = acc4[3];
                }
            }
        }
    }
}

// ======================= fused reductions =======================
// G: sum Z slices over computed lower band, mirror the rest, emit fp16 hi/lo.
__global__ void reduce_mirror_split(const float* __restrict__ part,
                                    __half* __restrict__ hi,
                                    __half* __restrict__ lo, int Z) {
    __shared__ float t[32][33];
    const int C = blockIdx.x * 32, R = blockIdx.y * 32;
    const int X = threadIdx.x, Y = threadIdx.y;
    const bool computed = ((C >> 7) <= 2 * (R >> 8) + 1);
    if (computed) {
        #pragma unroll
        for (int i = 0; i < 32; i += 8) {
            size_t o = (size_t)(R + Y + i) * H + C + X;
            float s = part[o];
            for (int zz = 1; zz < Z; zz++) s += part[o + (size_t)zz * H * H];
            __half h, l; fp16_split(s, h, l);
            hi[o] = h; lo[o] = l;
        }
    } else {
        #pragma unroll
        for (int i = 0; i < 32; i += 8) {
            size_t o = (size_t)(C + Y + i) * H + R + X;   // mirrored source
            float s = part[o];
            for (int zz = 1; zz < Z; zz++) s += part[o + (size_t)zz * H * H];
            t[Y + i][X] = s;
        }
        __syncthreads();
        #pragma unroll
        for (int i = 0; i < 32; i += 8) {
            float v = t[X][Y + i];
            size_t o = (size_t)(R + Y + i) * H + C + X;
            __half h, l; fp16_split(v, h, l);
            hi[o] = h; lo[o] = l;
        }
    }
}

// sum Z slices -> fp16 hi/lo (same layout)
__global__ void reduce_split_n(const float* __restrict__ part,
                               __half* __restrict__ hi,
                               __half* __restrict__ lo, int Z) {
    int i = blockIdx.x * 256 + threadIdx.x;
    float s = part[i];
    for (int zz = 1; zz < Z; zz++) s += part[i + (size_t)zz * H * H];
    __half h, l; fp16_split(s, h, l);
    hi[i] = h; lo[i] = l;
}

// P epilogue: sum Z slices of S = U Wv^T, add rank-2 (w1 bv^T + w2 vsp^T), *alpha,
// emit TRANSPOSED single fp16: pt[c][r] = alpha*(S[r][c] + w1[r]bv[c] + w2[r]vsp[c])
__global__ void reduce_t_rank2(const float* __restrict__ part, __half* __restrict__ hi,
                               const float* __restrict__ w1, const float* __restrict__ w2,
                               const float* __restrict__ bv, const float* __restrict__ vsp,
                               int Z, float alpha) {
    __shared__ float t[32][33];
    const int C = blockIdx.x * 32, R = blockIdx.y * 32;
    const int X = threadIdx.x, Y = threadIdx.y;
    #pragma unroll
    for (int i = 0; i < 32; i += 8) {
        const int r = R + Y + i, cc = C + X;
        size_t o = (size_t)r * H + cc;
        float s = part[o];
        for (int zz = 1; zz < Z; zz++) s += part[o + (size_t)zz * H * H];
        s += w1[r] * bv[cc] + w2[r] * vsp[cc];
        t[Y + i][X] = alpha * s;
    }
    __syncthreads();
    #pragma unroll
    for (int i = 0; i < 32; i += 8) {
        float v = t[X][Y + i];
        size_t o = (size_t)(C + Y + i) * H + R + X;
        hi[o] = __float2half(v);
    }
}

// ======================= split kernels =======================
__global__ void split_x_fused(const float* __restrict__ x,
                              __half* __restrict__ xh,
                              __half* __restrict__ xth, __half* __restrict__ xtl) {
    __shared__ float t[32][33];
    const int bxc = blockIdx.x * 32;
    const int byr = blockIdx.y * 32;
    const int X = threadIdx.x, Y = threadIdx.y;
    #pragma unroll
    for (int i = 0; i < 32; i += 8) {
        size_t o = (size_t)(byr + Y + i) * H + bxc + X;
        float v = x[o];
        t[Y + i][X] = v;
        xh[o] = __float2half(v);
    }
    __syncthreads();
    #pragma unroll
    for (int i = 0; i < 32; i += 8) {
        float v = t[X][Y + i];
        size_t o = (size_t)(bxc + Y + i) * NROWS + byr + X;
        __half h, l; fp16_split(v, h, l);
        xth[o] = h; xtl[o] = l;
    }
}
__global__ void split_n_kernel(const float* __restrict__ in, __half* __restrict__ hi,
                               __half* __restrict__ lo, int n) {
    int i = blockIdx.x * 256 + threadIdx.x;
    if (i < n) { __half h, l; fp16_split(in[i], h, l); hi[i] = h; lo[i] = l; }
}
__global__ void split_t_kernel(const float* __restrict__ in, __half* __restrict__ hi,
                               __half* __restrict__ lo, int R, int C) {
    __shared__ float t[32][33];
    const int bx = blockIdx.x * 32;
    const int by = blockIdx.y * 32;
    const int x = threadIdx.x, y = threadIdx.y;
    #pragma unroll
    for (int i = 0; i < 32; i += 8)
        t[y + i][x] = in[(size_t)(by + y + i) * C + bx + x];
    __syncthreads();
    #pragma unroll
    for (int i = 0; i < 32; i += 8) {
        float v = t[x][y + i];
        size_t o = (size_t)(bx + y + i) * R + by + x;
        __half h, l; fp16_split(v, h, l);
        hi[o] = h; lo[o] = l;
    }
}

// ======================= small SIMT helpers =======================
__global__ void colsum_part(const float* __restrict__ x, float* __restrict__ part) {
    int j = blockIdx.x * 256 + threadIdx.x;
    int nb = blockIdx.y;
    float s = 0.f;
    int n0 = nb * (NROWS / 32);
    for (int n = n0; n < n0 + (NROWS / 32); n++) s += x[n * H + j];
    part[nb * H + j] = s;
}
__global__ void reduce_part(const float* __restrict__ part, float* __restrict__ out,
                            int cnt, float scale) {
    int j = blockIdx.x * 256 + threadIdx.x;
    float s = 0.f;
    for (int i = 0; i < cnt; i++) s += part[i * H + j];
    out[j] = s * scale;
}
__global__ void matvec_k(const float* __restrict__ W, const float* __restrict__ v,
                         float* __restrict__ out) {
    int row = blockIdx.x * 8 + (threadIdx.x >> 5);
    int lane = threadIdx.x & 31;
    float s = 0.f;
    for (int k = lane; k < H; k += 32) s += W[row * H + k] * v[k];
    #pragma unroll
    for (int o = 16; o > 0; o >>= 1) s += __shfl_xor_sync(0xffffffffu, s, o);
    if (lane == 0) out[row] = s;
}
// column matvec partials: part[ib][j] = sum_{i in band ib} Mx[i][j] * b[i]
__global__ void cvec_part(const float* __restrict__ Mx, const float* __restrict__ b,
                          float* __restrict__ part) {
    int j = blockIdx.x * 256 + threadIdx.x;
    int ib = blockIdx.y;
    float s = 0.f;
    for (int i = ib * 64; i < ib * 64 + 64; i++) s += Mx[i * H + j] * b[i];
    part[ib * H + j] = s;
}
// vsp = vs + N*bv
__global__ void vsp_kernel(const float* __restrict__ vs, const float* __restrict__ bv,
                           float* __restrict__ vsp) {
    int j = blockIdx.x * 256 + threadIdx.x;
    vsp[j] = vs[j] + 8192.0f * bv[j];
}
// d[0] = ks.bq ; d[1] = bk.bq
__global__ void dot2_kernel(const float* __restrict__ ks, const float* __restrict__ bk,
                            const float* __restrict__ bq, float* __restrict__ d) {
    __shared__ float r0s[256], r1s[256];
    int t = threadIdx.x;
    float a = 0.f, b = 0.f;
    for (int k = t; k < H; k += 256) { a += ks[k] * bq[k]; b += bk[k] * bq[k]; }
    r0s[t] = a; r1s[t] = b;
    __syncthreads();
    for (int o = 128; o > 0; o >>= 1) {
        if (t < o) { r0s[t] += r0s[t + o]; r1s[t] += r1s[t + o]; }
        __syncthreads();
    }
    if (t == 0) { d[0] = r0s[0]; d[1] = r1s[0]; }
}
// u2 = (gh + gl) @ u1
__global__ void matvec_g(const __half* __restrict__ gh, const __half* __restrict__ gl,
                         const float* __restrict__ u1, float* __restrict__ u2) {
    int row = blockIdx.x * 8 + (threadIdx.x >> 5);
    int lane = threadIdx.x & 31;
    float s = 0.f;
    for (int k = lane; k < H; k += 32) {
        size_t o = (size_t)row * H + k;
        s += (__half2float(gh[o]) + __half2float(gl[o])) * u1[k];
    }
    #pragma unroll
    for (int o = 16; o > 0; o >>= 1) s += __shfl_xor_sync(0xffffffffu, s, o);
    if (lane == 0) u2[row] = s;
}
// c_j = scale * ( Wv[j,:].u2 + bv[j]*d0 + vsp[j]*d1 )
__global__ void cfinal_kernel(const float* __restrict__ Wv, const float* __restrict__ u2,
                              const float* __restrict__ bv, const float* __restrict__ vsp,
                              const float* __restrict__ d, float* __restrict__ c, float scale) {
    int row = blockIdx.x * 8 + (threadIdx.x >> 5);
    int lane = threadIdx.x & 31;
    float s = 0.f;
    for (int k = lane; k < H; k += 32) s += Wv[row * H + k] * u2[k];
    #pragma unroll
    for (int o = 16; o > 0; o >>= 1) s += __shfl_xor_sync(0xffffffffu, s, o);
    if (lane == 0) c[row] = scale * (s + bv[row] * d[0] + vsp[row] * d[1]);
}

// ======================= launch =======================
extern "C" void kernel_launch(void* const* d_in, const int* in_sizes, int n_in,
                              void* d_out, int out_size) {
    const float* x  = (const float*)d_in[0];
    const float* Wq = (const float*)d_in[1];
    const float* bq = (const float*)d_in[2];
    const float* Wk = (const float*)d_in[3];
    const float* bk = (const float*)d_in[4];
    const float* Wv = (const float*)d_in[5];
    const float* bv = (const float*)d_in[6];
    float* out = (float*)d_out;

    cudaFuncSetAttribute(mma_gemm, cudaFuncAttributeMaxDynamicSharedMemorySize, GSMEM);

    // streams/events created once, on the (uncaptured) correctness call
    static cudaStream_t s2 = nullptr;
    static cudaEvent_t evRoot, evB, evG, evC;
    if (!s2) {
        cudaStreamCreateWithFlags(&s2, cudaStreamNonBlocking);
        cudaEventCreateWithFlags(&evRoot, cudaEventDisableTiming);
        cudaEventCreateWithFlags(&evB, cudaEventDisableTiming);
        cudaEventCreateWithFlags(&evG, cudaEventDisableTiming);
        cudaEventCreateWithFlags(&evC, cudaEventDisableTiming);
    }

    float *cpart, *spart, *s, *ks, *vs, *vsp, *c, *u1, *u2, *w1, *w2, *d2;
    cudaGetSymbolAddress((void**)&cpart, g_cpart);
    cudaGetSymbolAddress((void**)&spart, g_spart);
    cudaGetSymbolAddress((void**)&s, g_s);
    cudaGetSymbolAddress((void**)&ks, g_ks);
    cudaGetSymbolAddress((void**)&vs, g_vs);
    cudaGetSymbolAddress((void**)&vsp, g_vsp);
    cudaGetSymbolAddress((void**)&c, g_c);
    cudaGetSymbolAddress((void**)&u1, g_u1);
    cudaGetSymbolAddress((void**)&u2, g_u2);
    cudaGetSymbolAddress((void**)&w1, g_w1);
    cudaGetSymbolAddress((void**)&w2, g_w2);
    cudaGetSymbolAddress((void**)&d2, g_d2);

    __half *xt_hi, *xt_lo, *x_h, *wkt_hi, *wkt_lo, *wv_hi, *wv_lo;
    __half *wqt_hi, *wqt_lo, *a1h, *a1l, *gh, *gl, *uh, *ul, *pt_h;
    cudaGetSymbolAddress((void**)&xt_hi, g_xt_hi);
    cudaGetSymbolAddress((void**)&xt_lo, g_xt_lo);
    cudaGetSymbolAddress((void**)&x_h,  g_x_h);
    cudaGetSymbolAddress((void**)&wkt_hi, g_wkt_hi);
    cudaGetSymbolAddress((void**)&wkt_lo, g_wkt_lo);
    cudaGetSymbolAddress((void**)&wv_hi, g_wv_hi);
    cudaGetSymbolAddress((void**)&wv_lo, g_wv_lo);
    cudaGetSymbolAddress((void**)&wqt_hi, g_wqt_hi);
    cudaGetSymbolAddress((void**)&wqt_lo, g_wqt_lo);
    cudaGetSymbolAddress((void**)&a1h, g_a1_hi);
    cudaGetSymbolAddress((void**)&a1l, g_a1_lo);
    cudaGetSymbolAddress((void**)&gh, g_g_hi);
    cudaGetSymbolAddress((void**)&gl, g_g_lo);
    cudaGetSymbolAddress((void**)&uh, g_u_hi);
    cudaGetSymbolAddress((void**)&ul, g_u_lo);
    cudaGetSymbolAddress((void**)&pt_h, g_pt_h);

    const float inv_sqrt_h = 0.03125f;
    const size_t PS = (size_t)H * H;
    float* a1f32 = cpart + 7 * PS;   // fp32 scratch for A1 (disjoint from ata's slices 0..6)
    dim3 tb(32, 8);

    // ======== fork ========
    cudaEventRecord(evRoot, 0);
    cudaStreamWaitEvent(s2, evRoot, 0);

    // ---- branch B (s2): weights, vectors, A1 = Wq^T Wk ----
    split_t_kernel<<<dim3(H / 32, H / 32), tb, 0, s2>>>(Wq, wqt_hi, wqt_lo, H, H);
    split_t_kernel<<<dim3(H / 32, H / 32), tb, 0, s2>>>(Wk, wkt_hi, wkt_lo, H, H);
    split_n_kernel<<<(H * H) / 256, 256, 0, s2>>>(Wv, wv_hi, wv_lo, H * H);
    colsum_part<<<dim3(4, 32), 256, 0, s2>>>(x, spart);
    reduce_part<<<4, 256, 0, s2>>>(spart, s, 32, 1.0f);
    matvec_k<<<128, 256, 0, s2>>>(Wk, s, ks);
    matvec_k<<<128, 256, 0, s2>>>(Wv, s, vs);
    vsp_kernel<<<4, 256, 0, s2>>>(vs, bv, vsp);
    cvec_part<<<dim3(4, 16), 256, 0, s2>>>(Wk, bq, spart);     // u1 = Wk^T bq
    reduce_part<<<4, 256, 0, s2>>>(spart, u1, 16, 1.0f);
    cvec_part<<<dim3(4, 16), 256, 0, s2>>>(Wq, ks, spart);     // w1 = Wq^T ks
    reduce_part<<<4, 256, 0, s2>>>(spart, w1, 16, 1.0f);
    cvec_part<<<dim3(4, 16), 256, 0, s2>>>(Wq, bk, spart);     // w2 = Wq^T bk
    reduce_part<<<4, 256, 0, s2>>>(spart, w2, 16, 1.0f);
    dot2_kernel<<<1, 256, 0, s2>>>(ks, bk, bq, d2);
    {   // A1 = Wq^T Wk  (3-term, Z=1, 32 CTAs -> overlaps ata)
        GemmArgs a = {wqt_hi, wqt_hi, wqt_lo,  wkt_hi, wkt_lo, wkt_hi,
                      H, H, H, a1f32, H, 1.0f, nullptr, 0, 0, 3};
        mma_gemm<<<dim3(8, 4, 1), 256, GSMEM, s2>>>(a);
    }
    split_n_kernel<<<(H * H) / 256, 256, 0, s2>>>(a1f32, a1h, a1l, H * H);
    cudaEventRecord(evB, s2);

    // ---- main: x splits, G = x^T x (band, Z=7 -> 140 CTAs single wave) ----
    split_x_fused<<<dim3(H / 32, NROWS / 32), tb>>>(x, x_h, xt_hi, xt_lo);
    {
        GemmArgs a = {xt_hi, xt_hi, xt_lo,  xt_hi, xt_lo, xt_hi,
                      NROWS, NROWS, NROWS, cpart, H, 1.0f, nullptr, PS, 1, 3};
        mma_gemm<<<dim3(20, 1, 7), 256, GSMEM>>>(a);
    }
    reduce_mirror_split<<<dim3(32, 32), tb>>>(cpart, gh, gl, 7);
    cudaEventRecord(evG, 0);

    // ---- branch B2 (s2): c-vector chain (needs G + branch-B vectors) ----
    cudaStreamWaitEvent(s2, evG, 0);
    matvec_g<<<128, 256, 0, s2>>>(gh, gl, u1, u2);                 // u2 = G u1
    cfinal_kernel<<<128, 256, 0, s2>>>(Wv, u2, bv, vsp, d2, c, inv_sqrt_h);
    cudaEventRecord(evC, s2);

    // ---- main: U = A1 @ G  (3-term, Z=4) ----
    cudaStreamWaitEvent(0, evB, 0);
    {
        GemmArgs a = {a1h, a1h, a1l,  gh, gl, gh,
                      H, H, H, cpart, H, 1.0f, nullptr, PS, 0, 3};
        mma_gemm<<<dim3(8, 4, 4), 256, GSMEM>>>(a);
    }
    reduce_split_n<<<4096, 256>>>(cpart, uh, ul, 4);

    // ---- main: P = U @ Wv^T /32 + rank-2, emitted as transposed fp16 ----
    {
        GemmArgs a = {uh, uh, ul,  wv_hi, wv_lo, wv_hi,
                      H, H, H, cpart, H, 1.0f, nullptr, PS, 0, 3};
        mma_gemm<<<dim3(8, 4, 4), 256, GSMEM>>>(a);
    }
    reduce_t_rank2<<<dim3(32, 32), tb>>>(cpart, pt_h, w1, w2, bv, vsp, 4, inv_sqrt_h);

    // ---- main: out = x @ P + 1 c^T (single fp16 term, fused epilogue) ----
    cudaStreamWaitEvent(0, evC, 0);
    {
        GemmArgs a = {x_h, x_h, x_h,  pt_h, pt_h, pt_h,
                      H, H, H, out, H, 1.0f, c, 0, 0, 1};
        mma_gemm<<<dim3(8, NROWS / 256, 1), 256, GSMEM>>>(a);
    }
}

// round 13
// speedup vs baseline: 1.1201x; 1.1201x over previous
#include <cuda_runtime.h>
#include <cuda_fp16.h>
#include <cstdint>
#include <cstddef>

#define NROWS 8192
#define H 1024

// ======================= helpers =======================
__device__ __forceinline__ uint32_t smem_to_u32(const void* p) {
    uint32_t a;
    asm("{ .reg .u64 t; cvta.to.shared.u64 t, %1; cvt.u32.u64 %0, t; }" : "=r"(a) : "l"(p));
    return a;
}
__device__ __forceinline__ void ldmatrix_x4(uint32_t* r, uint32_t addr) {
    asm volatile("ldmatrix.sync.aligned.m8n8.x4.shared.b16 {%0,%1,%2,%3}, [%4];"
                 : "=r"(r[0]), "=r"(r[1]), "=r"(r[2]), "=r"(r[3]) : "r"(addr));
}
__device__ __forceinline__ void mma_16816(float* d, const uint32_t* a, uint32_t b0, uint32_t b1) {
    asm volatile(
        "mma.sync.aligned.m16n8k16.row.col.f32.f16.f16.f32 "
        "{%0,%1,%2,%3}, {%4,%5,%6,%7}, {%8,%9}, {%0,%1,%2,%3};"
        : "+f"(d[0]), "+f"(d[1]), "+f"(d[2]), "+f"(d[3])
        : "r"(a[0]), "r"(a[1]), "r"(a[2]), "r"(a[3]), "r"(b0), "r"(b1));
}
__device__ __forceinline__ void cp_async16(uint32_t saddr, const void* gaddr) {
    asm volatile("cp.async.cg.shared.global [%0], [%1], 16;" :: "r"(saddr), "l"(gaddr));
}
__device__ __forceinline__ void fp16_split(float v, __half& h, __half& l) {
    h = __float2half(v);
    l = __float2half(v - __half2float(h));
}

// ======================= scratch (device globals only) =======================
__device__ __align__(256) float g_cpart[8 * H * H];   // split-K partials
__device__ __align__(256) float g_spart[64 * H];
__device__ float g_s[H];
__device__ float g_ks[H];
__device__ float g_vs[H];
__device__ float g_vsp[H];
__device__ float g_c[H];
__device__ float g_u1[H];
__device__ float g_u2[H];
__device__ float g_w1[H];
__device__ float g_w2[H];
__device__ float g_d2[2];

__device__ __align__(256) __half g_xt_hi[H * NROWS];   // x^T fp16 hi/lo
__device__ __align__(256) __half g_xt_lo[H * NROWS];
__device__ __align__(256) __half g_x_h[NROWS * H];     // fp16(x), direct layout
__device__ __align__(256) __half g_wkt_hi[H * H], g_wkt_lo[H * H];  // Wk^T split
__device__ __align__(256) __half g_wv_hi[H * H],  g_wv_lo[H * H];   // Wv split (row-major)
__device__ __align__(256) __half g_wqt_hi[H * H], g_wqt_lo[H * H];  // Wq^T split
__device__ __align__(256) __half g_a1_hi[H * H],  g_a1_lo[H * H];   // A1 = Wq^T Wk split
__device__ __align__(256) __half g_g_hi[H * H],   g_g_lo[H * H];    // G split (symmetric)
__device__ __align__(256) __half g_u_hi[H * H],   g_u_lo[H * H];    // U = A1 G split
__device__ __align__(256) __half g_pt_h[H * H];        // fp16(P)^T, single term

// ======================= HMMA GEMM: C = alpha * A @ B^T (+ addvec) =======================
struct GemmArgs {
    const __half* A0; const __half* A1; const __half* A2;
    const __half* B0; const __half* B1; const __half* B2;
    int lda, ldb, Kseg;
    float* C; int ldc;
    float alpha;                 // applied only when Z==1
    const float* addvec;         // only when Z==1; may be null
    size_t partStride;           // slice stride when Z>1
    int tri;
    int nseg;
};

#define STAGE   49152                        // A 32KB + B 16KB
#define NSTAGE  3
#define GSMEM   (NSTAGE * STAGE)             // 147456

__global__ void __launch_bounds__(256, 1) mma_gemm(GemmArgs g) {
    extern __shared__ char smem[];
    const uint32_t sbase = smem_to_u32(smem);
    const int tid = threadIdx.x;
    const int wid = tid >> 5, lane = tid & 31;
    int bx, by;
    if (g.tri) {   // lower-band blocks: cumulative bases {0,2,6,12}
        const int idx = blockIdx.x;
        by = (idx < 2) ? 0 : (idx < 6) ? 1 : (idx < 12) ? 2 : 3;
        bx = idx - by * (by + 1);
    } else { bx = blockIdx.x; by = blockIdx.y; }
    const int m0 = by * 256, n0 = bx * 128;
    const int z = blockIdx.z, Z = gridDim.z;

    const int cps = g.Kseg >> 6;
    const int total = cps * g.nseg;
    const int ncz = (total + Z - 1) / Z;       // ceil
    const int c0 = z * ncz;
    const int c1 = (c0 + ncz < total) ? (c0 + ncz) : total;

    const __half* As[3] = {g.A0, g.A1, g.A2};
    const __half* Bs[3] = {g.B0, g.B1, g.B2};

    const int lrow = tid >> 3;          // 0..31
    const int lc16 = tid & 7;           // 16B column group

    auto issue = [&](int c, int st) {
        const int seg = c / cps;
        const int k0 = (c - seg * cps) << 6;
        const __half* Ap = As[seg] + (size_t)m0 * g.lda + k0;
        const __half* Bp = Bs[seg] + (size_t)n0 * g.ldb + k0;
        const uint32_t abase = sbase + st * STAGE;
        const uint32_t bbase = abase + 32768;
        #pragma unroll
        for (int p = 0; p < 8; p++) {   // A: 256 rows
            const int row = lrow + p * 32;
            const uint32_t so = row * 128 + ((lc16 ^ (row & 7)) << 4);
            cp_async16(abase + so, Ap + (size_t)row * g.lda + lc16 * 8);
        }
        #pragma unroll
        for (int p = 0; p < 4; p++) {   // B: 128 rows
            const int row = lrow + p * 32;
            const uint32_t so = row * 128 + ((lc16 ^ (row & 7)) << 4);
            cp_async16(bbase + so, Bp + (size_t)row * g.ldb + lc16 * 8);
        }
        asm volatile("cp.async.commit_group;" ::: "memory");
    };

    const int wm = wid >> 1;            // 0..3 -> 64 rows
    const int wn = wid & 1;             // 0..1 -> 64 cols
    const int t15 = lane & 15;
    const int khalf = (lane >> 4) & 1;

    float acc[4][8][4];
    #pragma unroll
    for (int i = 0; i < 4; i++)
        #pragma unroll
        for (int j = 0; j < 8; j++)
            #pragma unroll
            for (int q = 0; q < 4; q++) acc[i][j][q] = 0.f;

    if (c0 < c1) {
        issue(c0, 0);
        if (c0 + 1 < c1) issue(c0 + 1, 1);
        for (int c = c0; c < c1; c++) {
            const int st = (c - c0) % NSTAGE;
            if (c + 1 < c1) asm volatile("cp.async.wait_group 1;" ::: "memory");
            else            asm volatile("cp.async.wait_group 0;" ::: "memory");
            __syncthreads();
            if (c + 2 < c1) issue(c + 2, (st + 2) % NSTAGE);

            const uint32_t abase = sbase + st * STAGE;
            const uint32_t bbase = abase + 32768;
            #pragma unroll
            for (int kk = 0; kk < 4; kk++) {
                const int c16 = kk * 2 + khalf;
                uint32_t afr[4][4], bfr[4][4];
                #pragma unroll
                for (int mt = 0; mt < 4; mt++) {
                    const int row = wm * 64 + mt * 16 + t15;
                    ldmatrix_x4(afr[mt], abase + row * 128 + ((c16 ^ (row & 7)) << 4));
                }
                #pragma unroll
                for (int nt = 0; nt < 4; nt++) {
                    const int row = wn * 64 + nt * 16 + t15;
                    ldmatrix_x4(bfr[nt], bbase + row * 128 + ((c16 ^ (row & 7)) << 4));
                }
                #pragma unroll
                for (int mt = 0; mt < 4; mt++) {
                    #pragma unroll
                    for (int nt = 0; nt < 4; nt++) {
                        mma_16816(acc[mt][nt * 2 + 0], afr[mt], bfr[nt][0], bfr[nt][2]);
                        mma_16816(acc[mt][nt * 2 + 1], afr[mt], bfr[nt][1], bfr[nt][3]);
                    }
                }
            }
            __syncthreads();
        }
    }

    float* Cb = (Z == 1) ? g.C : (g.C + (size_t)z * g.partStride);
    #pragma unroll
    for (int mt = 0; mt < 4; mt++) {
        const int row = m0 + wm * 64 + mt * 16 + (lane >> 2);
        #pragma unroll
        for (int nt = 0; nt < 4; nt++) {
            #pragma unroll
            for (int gg = 0; gg < 2; gg++) {
                const int col = n0 + wn * 64 + nt * 16 + gg * 8 + 2 * (lane & 3);
                float* acc4 = acc[mt][nt * 2 + gg];
                float* p0 = Cb + (size_t)row * g.ldc + col;
                float* p1 = p0 + 8 * g.ldc;
                if (Z == 1) {
                    float av0 = 0.f, av1 = 0.f;
                    if (g.addvec) { av0 = g.addvec[col]; av1 = g.addvec[col + 1]; }
                    p0[0] = g.alpha * acc4[0] + av0;
                    p0[1] = g.alpha * acc4[1] + av1;
                    p1[0] = g.alpha * acc4[2] + av0;
                    p1[1] = g.alpha * acc4[3] + av1;
                } else {
                    p0[0] = acc4[0]; p0[1] = acc4[1];
                    p1[0] = acc4[2]; p1[1] = acc4[3];
                }
            }
        }
    }
}

// ======================= fused reductions =======================
__global__ void reduce_mirror_split(const float* __restrict__ part,
                                    __half* __restrict__ hi,
                                    __half* __restrict__ lo, int Z) {
    __shared__ float t[32][33];
    const int C = blockIdx.x * 32, R = blockIdx.y * 32;
    const int X = threadIdx.x, Y = threadIdx.y;
    const bool computed = ((C >> 7) <= 2 * (R >> 8) + 1);
    if (computed) {
        #pragma unroll
        for (int i = 0; i < 32; i += 8) {
            size_t o = (size_t)(R + Y + i) * H + C + X;
            float s = part[o];
            for (int zz = 1; zz < Z; zz++) s += part[o + (size_t)zz * H * H];
            __half h, l; fp16_split(s, h, l);
            hi[o] = h; lo[o] = l;
        }
    } else {
        #pragma unroll
        for (int i = 0; i < 32; i += 8) {
            size_t o = (size_t)(C + Y + i) * H + R + X;   // mirrored source
            float s = part[o];
            for (int zz = 1; zz < Z; zz++) s += part[o + (size_t)zz * H * H];
            t[Y + i][X] = s;
        }
        __syncthreads();
        #pragma unroll
        for (int i = 0; i < 32; i += 8) {
            float v = t[X][Y + i];
            size_t o = (size_t)(R + Y + i) * H + C + X;
            __half h, l; fp16_split(v, h, l);
            hi[o] = h; lo[o] = l;
        }
    }
}

__global__ void reduce_split_n(const float* __restrict__ part,
                               __half* __restrict__ hi,
                               __half* __restrict__ lo, int Z) {
    int i = blockIdx.x * 256 + threadIdx.x;
    float s = part[i];
    for (int zz = 1; zz < Z; zz++) s += part[i + (size_t)zz * H * H];
    __half h, l; fp16_split(s, h, l);
    hi[i] = h; lo[i] = l;
}

// P epilogue: sum Z slices of S = U Wv^T, add rank-2, *alpha, emit transposed fp16
__global__ void reduce_t_rank2(const float* __restrict__ part, __half* __restrict__ hi,
                               const float* __restrict__ w1, const float* __restrict__ w2,
                               const float* __restrict__ bv, const float* __restrict__ vsp,
                               int Z, float alpha) {
    __shared__ float t[32][33];
    const int C = blockIdx.x * 32, R = blockIdx.y * 32;
    const int X = threadIdx.x, Y = threadIdx.y;
    #pragma unroll
    for (int i = 0; i < 32; i += 8) {
        const int r = R + Y + i, cc = C + X;
        size_t o = (size_t)r * H + cc;
        float s = part[o];
        for (int zz = 1; zz < Z; zz++) s += part[o + (size_t)zz * H * H];
        s += w1[r] * bv[cc] + w2[r] * vsp[cc];
        t[Y + i][X] = alpha * s;
    }
    __syncthreads();
    #pragma unroll
    for (int i = 0; i < 32; i += 8) {
        float v = t[X][Y + i];
        size_t o = (size_t)(C + Y + i) * H + R + X;
        hi[o] = __float2half(v);
    }
}

// ======================= split kernels =======================
__global__ void split_x_fused(const float* __restrict__ x,
                              __half* __restrict__ xh,
                              __half* __restrict__ xth, __half* __restrict__ xtl) {
    __shared__ float t[32][33];
    const int bxc = blockIdx.x * 32;
    const int byr = blockIdx.y * 32;
    const int X = threadIdx.x, Y = threadIdx.y;
    #pragma unroll
    for (int i = 0; i < 32; i += 8) {
        size_t o = (size_t)(byr + Y + i) * H + bxc + X;
        float v = x[o];
        t[Y + i][X] = v;
        xh[o] = __float2half(v);
    }
    __syncthreads();
    #pragma unroll
    for (int i = 0; i < 32; i += 8) {
        float v = t[X][Y + i];
        size_t o = (size_t)(bxc + Y + i) * NROWS + byr + X;
        __half h, l; fp16_split(v, h, l);
        xth[o] = h; xtl[o] = l;
    }
}
__global__ void split_n_kernel(const float* __restrict__ in, __half* __restrict__ hi,
                               __half* __restrict__ lo, int n) {
    int i = blockIdx.x * 256 + threadIdx.x;
    if (i < n) { __half h, l; fp16_split(in[i], h, l); hi[i] = h; lo[i] = l; }
}
__global__ void split_t_kernel(const float* __restrict__ in, __half* __restrict__ hi,
                               __half* __restrict__ lo, int R, int C) {
    __shared__ float t[32][33];
    const int bx = blockIdx.x * 32;
    const int by = blockIdx.y * 32;
    const int x = threadIdx.x, y = threadIdx.y;
    #pragma unroll
    for (int i = 0; i < 32; i += 8)
        t[y + i][x] = in[(size_t)(by + y + i) * C + bx + x];
    __syncthreads();
    #pragma unroll
    for (int i = 0; i < 32; i += 8) {
        float v = t[x][y + i];
        size_t o = (size_t)(bx + y + i) * R + by + x;
        __half h, l; fp16_split(v, h, l);
        hi[o] = h; lo[o] = l;
    }
}

// ======================= small SIMT helpers =======================
__global__ void colsum_part(const float* __restrict__ x, float* __restrict__ part) {
    int j = blockIdx.x * 256 + threadIdx.x;
    int nb = blockIdx.y;                      // grid.y = 64
    float s = 0.f;
    int n0 = nb * (NROWS / 64);
    for (int n = n0; n < n0 + (NROWS / 64); n++) s += x[n * H + j];
    part[nb * H + j] = s;
}
__global__ void reduce_part(const float* __restrict__ part, float* __restrict__ out,
                            int cnt, float scale) {
    int j = blockIdx.x * 256 + threadIdx.x;
    float s = 0.f;
    for (int i = 0; i < cnt; i++) s += part[i * H + j];
    out[j] = s * scale;
}
__global__ void matvec_k(const float* __restrict__ W, const float* __restrict__ v,
                         float* __restrict__ out) {
    int row = blockIdx.x * 8 + (threadIdx.x >> 5);
    int lane = threadIdx.x & 31;
    float s = 0.f;
    for (int k = lane; k < H; k += 32) s += W[row * H + k] * v[k];
    #pragma unroll
    for (int o = 16; o > 0; o >>= 1) s += __shfl_xor_sync(0xffffffffu, s, o);
    if (lane == 0) out[row] = s;
}
__global__ void cvec_part(const float* __restrict__ Mx, const float* __restrict__ b,
                          float* __restrict__ part) {
    int j = blockIdx.x * 256 + threadIdx.x;
    int ib = blockIdx.y;
    float s = 0.f;
    for (int i = ib * 64; i < ib * 64 + 64; i++) s += Mx[i * H + j] * b[i];
    part[ib * H + j] = s;
}
__global__ void vsp_kernel(const float* __restrict__ vs, const float* __restrict__ bv,
                           float* __restrict__ vsp) {
    int j = blockIdx.x * 256 + threadIdx.x;
    vsp[j] = vs[j] + 8192.0f * bv[j];
}
__global__ void dot2_kernel(const float* __restrict__ ks, const float* __restrict__ bk,
                            const float* __restrict__ bq, float* __restrict__ d) {
    __shared__ float r0s[256], r1s[256];
    int t = threadIdx.x;
    float a = 0.f, b = 0.f;
    for (int k = t; k < H; k += 256) { a += ks[k] * bq[k]; b += bk[k] * bq[k]; }
    r0s[t] = a; r1s[t] = b;
    __syncthreads();
    for (int o = 128; o > 0; o >>= 1) {
        if (t < o) { r0s[t] += r0s[t + o]; r1s[t] += r1s[t + o]; }
        __syncthreads();
    }
    if (t == 0) { d[0] = r0s[0]; d[1] = r1s[0]; }
}
__global__ void matvec_g(const __half* __restrict__ gh, const __half* __restrict__ gl,
                         const float* __restrict__ u1, float* __restrict__ u2) {
    int row = blockIdx.x * 8 + (threadIdx.x >> 5);
    int lane = threadIdx.x & 31;
    float s = 0.f;
    for (int k = lane; k < H; k += 32) {
        size_t o = (size_t)row * H + k;
        s += (__half2float(gh[o]) + __half2float(gl[o])) * u1[k];
    }
    #pragma unroll
    for (int o = 16; o > 0; o >>= 1) s += __shfl_xor_sync(0xffffffffu, s, o);
    if (lane == 0) u2[row] = s;
}
__global__ void cfinal_kernel(const float* __restrict__ Wv, const float* __restrict__ u2,
                              const float* __restrict__ bv, const float* __restrict__ vsp,
                              const float* __restrict__ d, float* __restrict__ c, float scale) {
    int row = blockIdx.x * 8 + (threadIdx.x >> 5);
    int lane = threadIdx.x & 31;
    float s = 0.f;
    for (int k = lane; k < H; k += 32) s += Wv[row * H + k] * u2[k];
    #pragma unroll
    for (int o = 16; o > 0; o >>= 1) s += __shfl_xor_sync(0xffffffffu, s, o);
    if (lane == 0) c[row] = scale * (s + bv[row] * d[0] + vsp[row] * d[1]);
}

// ======================= launch =======================
extern "C" void kernel_launch(void* const* d_in, const int* in_sizes, int n_in,
                              void* d_out, int out_size) {
    const float* x  = (const float*)d_in[0];
    const float* Wq = (const float*)d_in[1];
    const float* bq = (const float*)d_in[2];
    const float* Wk = (const float*)d_in[3];
    const float* bk = (const float*)d_in[4];
    const float* Wv = (const float*)d_in[5];
    const float* bv = (const float*)d_in[6];
    float* out = (float*)d_out;

    cudaFuncSetAttribute(mma_gemm, cudaFuncAttributeMaxDynamicSharedMemorySize, GSMEM);

    static cudaStream_t s2 = nullptr;
    static cudaEvent_t evRoot, evX, evB, evG, evC;
    if (!s2) {
        cudaStreamCreateWithFlags(&s2, cudaStreamNonBlocking);
        cudaEventCreateWithFlags(&evRoot, cudaEventDisableTiming);
        cudaEventCreateWithFlags(&evX, cudaEventDisableTiming);
        cudaEventCreateWithFlags(&evB, cudaEventDisableTiming);
        cudaEventCreateWithFlags(&evG, cudaEventDisableTiming);
        cudaEventCreateWithFlags(&evC, cudaEventDisableTiming);
    }

    float *cpart, *spart, *s, *ks, *vs, *vsp, *c, *u1, *u2, *w1, *w2, *d2;
    cudaGetSymbolAddress((void**)&cpart, g_cpart);
    cudaGetSymbolAddress((void**)&spart, g_spart);
    cudaGetSymbolAddress((void**)&s, g_s);
    cudaGetSymbolAddress((void**)&ks, g_ks);
    cudaGetSymbolAddress((void**)&vs, g_vs);
    cudaGetSymbolAddress((void**)&vsp, g_vsp);
    cudaGetSymbolAddress((void**)&c, g_c);
    cudaGetSymbolAddress((void**)&u1, g_u1);
    cudaGetSymbolAddress((void**)&u2, g_u2);
    cudaGetSymbolAddress((void**)&w1, g_w1);
    cudaGetSymbolAddress((void**)&w2, g_w2);
    cudaGetSymbolAddress((void**)&d2, g_d2);

    __half *xt_hi, *xt_lo, *x_h, *wkt_hi, *wkt_lo, *wv_hi, *wv_lo;
    __half *wqt_hi, *wqt_lo, *a1h, *a1l, *gh, *gl, *uh, *ul, *pt_h;
    cudaGetSymbolAddress((void**)&xt_hi, g_xt_hi);
    cudaGetSymbolAddress((void**)&xt_lo, g_xt_lo);
    cudaGetSymbolAddress((void**)&x_h,  g_x_h);
    cudaGetSymbolAddress((void**)&wkt_hi, g_wkt_hi);
    cudaGetSymbolAddress((void**)&wkt_lo, g_wkt_lo);
    cudaGetSymbolAddress((void**)&wv_hi, g_wv_hi);
    cudaGetSymbolAddress((void**)&wv_lo, g_wv_lo);
    cudaGetSymbolAddress((void**)&wqt_hi, g_wqt_hi);
    cudaGetSymbolAddress((void**)&wqt_lo, g_wqt_lo);
    cudaGetSymbolAddress((void**)&a1h, g_a1_hi);
    cudaGetSymbolAddress((void**)&a1l, g_a1_lo);
    cudaGetSymbolAddress((void**)&gh, g_g_hi);
    cudaGetSymbolAddress((void**)&gl, g_g_lo);
    cudaGetSymbolAddress((void**)&uh, g_u_hi);
    cudaGetSymbolAddress((void**)&ul, g_u_lo);
    cudaGetSymbolAddress((void**)&pt_h, g_pt_h);

    const float inv_sqrt_h = 0.03125f;
    const size_t PS = (size_t)H * H;
    dim3 tb(32, 8);

    // ======== fork ========
    cudaEventRecord(evRoot, 0);
    cudaStreamWaitEvent(s2, evRoot, 0);

    // ---- s2: x split first (overlaps main's A1 pipeline), then light glue ----
    split_x_fused<<<dim3(H / 32, NROWS / 32), tb, 0, s2>>>(x, x_h, xt_hi, xt_lo);
    cudaEventRecord(evX, s2);
    split_n_kernel<<<(H * H) / 256, 256, 0, s2>>>(Wv, wv_hi, wv_lo, H * H);
    colsum_part<<<dim3(4, 64), 256, 0, s2>>>(x, spart);
    reduce_part<<<4, 256, 0, s2>>>(spart, s, 64, 1.0f);
    matvec_k<<<128, 256, 0, s2>>>(Wk, s, ks);
    matvec_k<<<128, 256, 0, s2>>>(Wv, s, vs);
    vsp_kernel<<<4, 256, 0, s2>>>(vs, bv, vsp);
    cvec_part<<<dim3(4, 16), 256, 0, s2>>>(Wk, bq, spart);     // u1 = Wk^T bq
    reduce_part<<<4, 256, 0, s2>>>(spart, u1, 16, 1.0f);
    cvec_part<<<dim3(4, 16), 256, 0, s2>>>(Wq, ks, spart);     // w1 = Wq^T ks
    reduce_part<<<4, 256, 0, s2>>>(spart, w1, 16, 1.0f);
    cvec_part<<<dim3(4, 16), 256, 0, s2>>>(Wq, bk, spart);     // w2 = Wq^T bk
    reduce_part<<<4, 256, 0, s2>>>(spart, w2, 16, 1.0f);
    dot2_kernel<<<1, 256, 0, s2>>>(ks, bk, bq, d2);
    cudaEventRecord(evB, s2);

    // ---- main: weight splits + A1 = Wq^T Wk (Z=4, 128 CTAs, full machine) ----
    split_t_kernel<<<dim3(H / 32, H / 32), tb>>>(Wq, wqt_hi, wqt_lo, H, H);
    split_t_kernel<<<dim3(H / 32, H / 32), tb>>>(Wk, wkt_hi, wkt_lo, H, H);
    {
        GemmArgs a = {wqt_hi, wqt_hi, wqt_lo,  wkt_hi, wkt_lo, wkt_hi,
                      H, H, H, cpart, H, 1.0f, nullptr, PS, 0, 3};
        mma_gemm<<<dim3(8, 4, 4), 256, GSMEM>>>(a);
    }
    reduce_split_n<<<4096, 256>>>(cpart, a1h, a1l, 4);

    // ---- main: ata (needs xt from s2). Z=7 -> 140 CTAs, single clean wave ----
    cudaStreamWaitEvent(0, evX, 0);
    {
        GemmArgs a = {xt_hi, xt_hi, xt_lo,  xt_hi, xt_lo, xt_hi,
                      NROWS, NROWS, NROWS, cpart, H, 1.0f, nullptr, PS, 1, 3};
        mma_gemm<<<dim3(20, 1, 7), 256, GSMEM>>>(a);
    }
    reduce_mirror_split<<<dim3(32, 32), tb>>>(cpart, gh, gl, 7);
    cudaEventRecord(evG, 0);

    // ---- s2: c-vector chain (needs G + glue vectors) ----
    cudaStreamWaitEvent(s2, evG, 0);
    matvec_g<<<128, 256, 0, s2>>>(gh, gl, u1, u2);
    cfinal_kernel<<<128, 256, 0, s2>>>(Wv, u2, bv, vsp, d2, c, inv_sqrt_h);
    cudaEventRecord(evC, s2);

    // ---- main: U = A1 @ G  (Z=4) ----
    {
        GemmArgs a = {a1h, a1h, a1l,  gh, gl, gh,
                      H, H, H, cpart, H, 1.0f, nullptr, PS, 0, 3};
        mma_gemm<<<dim3(8, 4, 4), 256, GSMEM>>>(a);
    }
    reduce_split_n<<<4096, 256>>>(cpart, uh, ul, 4);

    // ---- main: P = U @ Wv^T /32 + rank-2 (needs wv + w1/w2/vsp from s2) ----
    cudaStreamWaitEvent(0, evB, 0);
    {
        GemmArgs a = {uh, uh, ul,  wv_hi, wv_lo, wv_hi,
                      H, H, H, cpart, H, 1.0f, nullptr, PS, 0, 3};
        mma_gemm<<<dim3(8, 4, 4), 256, GSMEM>>>(a);
    }
    reduce_t_rank2<<<dim3(32, 32), tb>>>(cpart, pt_h, w1, w2, bv, vsp, 4, inv_sqrt_h);

    // ---- main: out = x @ P + 1 c^T ----
    cudaStreamWaitEvent(0, evC, 0);
    {
        GemmArgs a = {x_h, x_h, x_h,  pt_h, pt_h, pt_h,
                      H, H, H, out, H, 1.0f, c, 0, 0, 1};
        mma_gemm<<<dim3(8, NROWS / 256, 1), 256, GSMEM>>>(a);
    }
}